// round 9
// baseline (speedup 1.0000x reference)
#include <cuda_runtime.h>
#include <cuda_fp16.h>

// Scratch (__device__ globals; zero-init at load). N = 100000 <= MAXN.
// Rotated zeroing lives in the NODE kernels (element read-then-zeroed):
//   g_deg : atomics in deg_kernel -> prep reads deg[i] then zeroes it
//   g_S   : atomics in scatter<0> -> t_kernel reads S[i] then zeroes it
//   g_acc : atomics in scatter<1> -> final reads acc[i] then zeroes it
// First call is correct because __device__ globals are zero-initialized.
#define MAXN (1 << 17)
__device__ __align__(16) float  g_deg[MAXN];
__device__ __align__(16) float  g_dinv[MAXN];
__device__ __align__(16) __half g_a[MAXN];    // dinv[i]*x[i]  (fp16, 200KB: fits smem)
__device__ __align__(16) float  g_S[MAXN];    // layer-1 aggregate (fp32 REDs)
__device__ __align__(16) __half g_u[MAXN];    // dinv[i]*t[i]  (fp16)
__device__ __align__(16) float  g_acc[MAXN];  // layer-2 aggregate

#define EPT 8                  // edges/thread for deg_kernel
#define SBLOCKS 148            // one scatter block per SM (single wave)
#define STHREADS 1024

// ---------------------------------------------------------------------------
// Node kernels
// ---------------------------------------------------------------------------

// dinv[i] = 1/sqrt(deg[i]+1)  (+1 = self loop); a[i] = dinv[i]*x[i] (fp16).
// Zeroes g_deg after consuming it.
__global__ void prep_kernel(const float* __restrict__ x, int n) {
    int i4 = (blockIdx.x * blockDim.x + threadIdx.x) * 4;
    if (i4 + 3 < n) {
        float4 xv = *reinterpret_cast<const float4*>(x + i4);
        float4 dv = *reinterpret_cast<const float4*>(g_deg + i4);
        *reinterpret_cast<float4*>(g_deg + i4) = make_float4(0.f, 0.f, 0.f, 0.f);
        float4 di;
        di.x = 1.0f / sqrtf(dv.x + 1.0f);
        di.y = 1.0f / sqrtf(dv.y + 1.0f);
        di.z = 1.0f / sqrtf(dv.z + 1.0f);
        di.w = 1.0f / sqrtf(dv.w + 1.0f);
        *reinterpret_cast<float4*>(g_dinv + i4) = di;
        *reinterpret_cast<__half2*>(g_a + i4)     = __floats2half2_rn(di.x * xv.x, di.y * xv.y);
        *reinterpret_cast<__half2*>(g_a + i4 + 2) = __floats2half2_rn(di.z * xv.z, di.w * xv.w);
    } else {
        for (int i = i4; i < n; i++) {
            float di = 1.0f / sqrtf(g_deg[i] + 1.0f);
            g_deg[i] = 0.0f;
            g_dinv[i] = di;
            g_a[i] = __float2half_rn(di * x[i]);
        }
    }
}

// s = dinv*(S'+a); t = MLP(s); u = dinv*t (fp16). Zeroes g_S after consuming it.
__global__ void t_kernel(const float* __restrict__ W1,
                         const float* __restrict__ b1,
                         const float* __restrict__ W2,
                         int n, int H) {
    int i = blockIdx.x * blockDim.x + threadIdx.x;
    if (i < n) {
        float di = g_dinv[i];
        float Sv = g_S[i];
        g_S[i] = 0.0f;
        float s  = di * (Sv + __half2float(g_a[i]));
        float acc = 0.0f;
        #pragma unroll 16
        for (int k = 0; k < H; k++) {
            float h = fmaf(__ldg(&W1[k]), s, __ldg(&b1[k]));
            h = fmaxf(h, 0.0f);
            acc = fmaf(h, __ldg(&W2[k]), acc);
        }
        g_u[i] = __float2half_rn(di * acc);
    }
}

// out[i] = dinv[i]*(acc[i] + u[i]) + b2. Zeroes g_acc after consuming it.
__global__ void final_kernel(const float* __restrict__ b2,
                             float* __restrict__ out, int n) {
    int i = blockIdx.x * blockDim.x + threadIdx.x;
    if (i < n) {
        float av = g_acc[i];
        g_acc[i] = 0.0f;
        out[i] = g_dinv[i] * (av + __half2float(g_u[i])) + __ldg(&b2[0]);
    }
}

// ---------------------------------------------------------------------------
// Edge kernels (pure index-load + RED)
// ---------------------------------------------------------------------------

// deg[col] += 1
__global__ void __launch_bounds__(256, 8)
deg_kernel(const int* __restrict__ col, int E) {
    int i = blockIdx.x * blockDim.x + threadIdx.x;
    int e = i * EPT;
    if (e + EPT - 1 < E) {
        int idx[EPT];
        #pragma unroll
        for (int v = 0; v < EPT / 4; v++) {
            int4 c = *reinterpret_cast<const int4*>(col + e + v * 4);
            idx[v * 4 + 0] = c.x; idx[v * 4 + 1] = c.y;
            idx[v * 4 + 2] = c.z; idx[v * 4 + 3] = c.w;
        }
        #pragma unroll
        for (int v = 0; v < EPT; v++) atomicAdd(&g_deg[idx[v]], 1.0f);
    } else {
        for (; e < E; e++) atomicAdd(&g_deg[col[e]], 1.0f);
    }
}

// Scatter pass: dst[col] += table[row], table cached in smem.
// PASS=0: g_a -> g_S.  PASS=1: g_u -> g_acc.
// Tables/dsts selected INSIDE device code (R7 lesson: never pass __device__
// globals as kernel args from host).
template <int PASS>
__global__ void __launch_bounds__(STHREADS, 1)
scatter_kernel(const int* __restrict__ row, const int* __restrict__ col,
               int E, int N) {
    extern __shared__ __half sh[];   // N halves (200KB for N=100K)

    float* dst = (PASS == 0) ? g_S : g_acc;

    int tid = blockIdx.x * blockDim.x + threadIdx.x;
    int nthreads = gridDim.x * blockDim.x;

    // cooperative smem copy of the gather table (int4-coalesced; over-read
    // past N stays within MAXN -> safe)
    {
        const __half* table = (PASS == 0) ? g_a : g_u;
        int nvec = (N * 2 + 15) / 16;
        const int4* src4 = reinterpret_cast<const int4*>(table);
        int4* sh4 = reinterpret_cast<int4*>(sh);
        for (int v = threadIdx.x; v < nvec; v += blockDim.x) sh4[v] = src4[v];
    }
    __syncthreads();

    // grid-stride over 8-edge groups: batch 8 LDS gathers, then 8 REDs
    int E8 = E & ~7;
    int stride = nthreads * 8;
    for (int e = tid * 8; e < E8; e += stride) {
        int4 r0 = *reinterpret_cast<const int4*>(row + e);
        int4 r1 = *reinterpret_cast<const int4*>(row + e + 4);
        int4 c0 = *reinterpret_cast<const int4*>(col + e);
        int4 c1 = *reinterpret_cast<const int4*>(col + e + 4);
        float v0 = __half2float(sh[r0.x]);
        float v1 = __half2float(sh[r0.y]);
        float v2 = __half2float(sh[r0.z]);
        float v3 = __half2float(sh[r0.w]);
        float v4 = __half2float(sh[r1.x]);
        float v5 = __half2float(sh[r1.y]);
        float v6 = __half2float(sh[r1.z]);
        float v7 = __half2float(sh[r1.w]);
        atomicAdd(&dst[c0.x], v0);
        atomicAdd(&dst[c0.y], v1);
        atomicAdd(&dst[c0.z], v2);
        atomicAdd(&dst[c0.w], v3);
        atomicAdd(&dst[c1.x], v4);
        atomicAdd(&dst[c1.y], v5);
        atomicAdd(&dst[c1.z], v6);
        atomicAdd(&dst[c1.w], v7);
    }
    // tail (<8 edges)
    if (tid == 0) {
        for (int e = E8; e < E; e++)
            atomicAdd(&dst[col[e]], __half2float(sh[row[e]]));
    }
}

// ---------------------------------------------------------------------------
// Launch
// ---------------------------------------------------------------------------

extern "C" void kernel_launch(void* const* d_in, const int* in_sizes, int n_in,
                              void* d_out, int out_size) {
    const float* x    = (const float*)d_in[0];
    const int*   eidx = (const int*)d_in[1];    // [2, E] int32
    const float* W1   = (const float*)d_in[2];
    const float* b1   = (const float*)d_in[3];
    const float* W2   = (const float*)d_in[4];
    const float* b2   = (const float*)d_in[5];
    float*       out  = (float*)d_out;

    int N = in_sizes[0];
    int E = in_sizes[1] / 2;
    int H = in_sizes[3];

    const int* row = eidx;
    const int* col = eidx + E;

    // Opt in to 200KB dynamic smem. Idempotent, not stream-ordered, not an
    // allocation -> capture-safe; called unconditionally (no static guards).
    int shBytes = ((N * 2 + 15) / 16) * 16;
    cudaFuncSetAttribute(scatter_kernel<0>,
                         cudaFuncAttributeMaxDynamicSharedMemorySize, 227 * 1024);
    cudaFuncSetAttribute(scatter_kernel<1>,
                         cudaFuncAttributeMaxDynamicSharedMemorySize, 227 * 1024);

    const int TB = 256;
    int nodeBlocks  = (N + TB - 1) / TB;
    int node4Blocks = ((N + 3) / 4 + TB - 1) / TB;
    int degBlocks   = ((E + EPT - 1) / EPT + TB - 1) / TB;

    deg_kernel<<<degBlocks, TB>>>(col, E);
    prep_kernel<<<node4Blocks, TB>>>(x, N);
    scatter_kernel<0><<<SBLOCKS, STHREADS, shBytes>>>(row, col, E, N);
    t_kernel<<<nodeBlocks, TB>>>(W1, b1, W2, N, H);
    scatter_kernel<1><<<SBLOCKS, STHREADS, shBytes>>>(row, col, E, N);
    final_kernel<<<nodeBlocks, TB>>>(b2, out, N);
}